// round 16
// baseline (speedup 1.0000x reference)
#include <cuda_runtime.h>
#include <cuda_fp16.h>
#include <math.h>
#include <stdint.h>

#define ENCD   1024
#define BATCH  32
#define SEQ    2048
#define MTOT   (BATCH * SEQ)   // 65536
#define NTILES 8               // 1024/128 n-tiles
#define NSTG   32              // K stages of 32
#define NCHUNK 16              // k4 S-chunks of 128

// Scratch (static device arrays: no allocation allowed).
__device__ __half g_ench[(size_t)MTOT * ENCD];   // fp16 copy of enc (128MB)
__device__ __half g_w1t[ENCD * ENCD];            // fp16 w1 TRANSPOSED [n][k]
__device__ float  g_q[BATCH * ENCD];
__device__ float  g_partials[NTILES * MTOT];
__device__ float  g_attn[MTOT];
__device__ float  g_ctx[NCHUNK][BATCH * ENCD];

// ---------------------------------------------------------------------------
__device__ __forceinline__ void mma_f16(float* d, const uint32_t* a, const uint32_t* b) {
    asm volatile(
        "mma.sync.aligned.m16n8k16.row.col.f32.f16.f16.f32 "
        "{%0,%1,%2,%3},{%4,%5,%6,%7},{%8,%9},{%0,%1,%2,%3};"
        : "+f"(d[0]), "+f"(d[1]), "+f"(d[2]), "+f"(d[3])
        : "r"(a[0]), "r"(a[1]), "r"(a[2]), "r"(a[3]), "r"(b[0]), "r"(b[1]));
}
#define LDSM4(r0, r1, r2, r3, addr)                                          \
    asm volatile("ldmatrix.sync.aligned.m8n8.x4.shared.b16 {%0,%1,%2,%3}, [%4];" \
                 : "=r"(r0), "=r"(r1), "=r"(r2), "=r"(r3) : "r"(addr))
__device__ __forceinline__ float tanh_fast(float x) {
    float xc = fminf(fmaxf(x, -9.0f), 9.0f);
    float y, r;
    asm("ex2.approx.f32 %0, %1;" : "=f"(y) : "f"(xc * 2.885390081777927f));
    asm("rcp.approx.f32 %0, %1;" : "=f"(r) : "f"(y + 1.0f));
    return (y - 1.0f) * r;
}
__device__ __forceinline__ uint32_t smem_u32(const void* p) {
    uint32_t a;
    asm("{ .reg .u64 t; cvta.to.shared.u64 t, %1; cvt.u32.u64 %0, t; }"
        : "=r"(a) : "l"(p));
    return a;
}
#define CP_ASYNC16(dst, src) \
    asm volatile("cp.async.cg.shared.global [%0], [%1], 16;" :: "r"(dst), "l"(src) : "memory")
#define CP_COMMIT()  asm volatile("cp.async.commit_group;" ::: "memory")
#define CP_WAIT2()   asm volatile("cp.async.wait_group 2;" ::: "memory")

// smem geometry (bytes). A stage: 128 m-rows x 80B (64B = 32 fp16 + 16B pad).
// B stage: 128 n-rows x 80B. 80B stride -> each 8-lane ldmatrix phase hits
// all 32 banks exactly once. 4-stage ring.
#define ASTG   10240
#define BSTG   10240
#define OFF_A  0
#define OFF_B  (4 * ASTG)            // 40960
#define OFF_QS (OFF_B + 4 * BSTG)    // 81920
#define OFF_VS (OFF_QS + 512)
#define OFF_SR (OFF_VS + 512)
#define SMTOT  (OFF_SR + 2048)       // 84992

// Fused prep kernel block ranges.
#define NB_Q   128                   // query blocks (4 e-chunks x 32 batches)
#define NB_W1T 1024                  // w1 transpose blocks (32 x 32 tiles)
#define NB_ENC 32768                 // enc convert blocks
#define NB_PREP (NB_Q + NB_W1T + NB_ENC)

// ---------------------------------------------------------------------------
// K0: fused prep (query GEMV | w1 transpose->fp16 | enc->fp16).
// ---------------------------------------------------------------------------
__global__ __launch_bounds__(256)
void k0_prep(const float* __restrict__ enc, const float* __restrict__ w1,
             const float* __restrict__ dec, const float* __restrict__ w2,
             const float* __restrict__ b1, const float* __restrict__ b2) {
    __shared__ float sh[1056];
    const int id = blockIdx.x;
    const int t  = threadIdx.x;

    if (id < NB_Q) {
        const int bx = id & 3, b = id >> 2;
        for (int i = t; i < ENCD; i += 256) sh[i] = dec[b * ENCD + i];
        __syncthreads();
        const int e = bx * 256 + t;
        float acc = 0.f;
        #pragma unroll 8
        for (int d = 0; d < ENCD; d++)
            acc += sh[d] * w2[(size_t)d * ENCD + e];
        g_q[b * ENCD + e] = acc + b1[e] + b2[e];
    } else if (id < NB_Q + NB_W1T) {
        const int tid = id - NB_Q;
        const int nb = (tid & 31) * 32, k0 = (tid >> 5) * 32;
        float (*tl)[33] = (float(*)[33])sh;
        const int tx = t & 31, ty = t >> 5;
        #pragma unroll
        for (int i = 0; i < 32; i += 8)
            tl[ty + i][tx] = w1[(size_t)(k0 + ty + i) * ENCD + nb + tx];
        __syncthreads();
        #pragma unroll
        for (int i = 0; i < 32; i += 8)
            g_w1t[(size_t)(nb + ty + i) * ENCD + k0 + tx] =
                __float2half_rn(tl[tx][ty + i]);
    } else {
        const size_t i = ((size_t)(id - NB_Q - NB_W1T) * 256 + t) * 8;
        float4 f0 = *(const float4*)(enc + i);
        float4 f1 = *(const float4*)(enc + i + 4);
        __half2 h0 = __floats2half2_rn(f0.x, f0.y);
        __half2 h1 = __floats2half2_rn(f0.z, f0.w);
        __half2 h2 = __floats2half2_rn(f1.x, f1.y);
        __half2 h3 = __floats2half2_rn(f1.z, f1.w);
        uint4 u;
        u.x = *(uint32_t*)&h0; u.y = *(uint32_t*)&h1;
        u.z = *(uint32_t*)&h2; u.w = *(uint32_t*)&h3;
        *(uint4*)(g_ench + i) = u;
    }
}

// ---------------------------------------------------------------------------
// K2: fused score GEMM, fp16 mma.sync m16n8k16 + ldmatrix.x4 fragments,
// cp.async 4-stage pipeline (R11 configuration — best measured).
// CTA tile 128x128, 8 warps 2(M)x4(N), warp 64x32. grid (8, 512), 256 thr.
// ---------------------------------------------------------------------------
__global__ __launch_bounds__(256, 2)
void k2_scores(const float* __restrict__ v) {
    extern __shared__ __align__(16) float smf[];
    const uint32_t sb = smem_u32(smf);
    float* qs   = smf + (OFF_QS >> 2);
    float* vs   = smf + (OFF_VS >> 2);
    float* sred = smf + (OFF_SR >> 2);

    const int nt = blockIdx.x, n0 = nt * 128;
    const int m0 = blockIdx.y * 128;
    const int b  = m0 / SEQ;
    const int t  = threadIdx.x;
    const int lane = t & 31, w = t >> 5;
    const int wm = w & 1, wn = w >> 1;
    const int g = lane >> 2, c = lane & 3;

    if (t < 128) { qs[t] = g_q[b * ENCD + n0 + t]; vs[t] = v[n0 + t]; }

    const int lrow  = ((lane >> 3) & 1) * 8 + (lane & 7);
    const int lkoff = (lane >> 4) * 16;
    const uint32_t aTile = sb + OFF_A + (wm * 64 + lrow) * 80 + lkoff;
    const uint32_t bTile = sb + OFF_B + (wn * 32 + lrow) * 80 + lkoff;

    const int r0 = t >> 2, r1 = r0 + 64, j = t & 3;
    const __half* aS0 = g_ench + (size_t)(m0 + r0) * ENCD + j * 8;
    const __half* aS1 = g_ench + (size_t)(m0 + r1) * ENCD + j * 8;
    const __half* bS0 = g_w1t + (size_t)(n0 + r0) * ENCD + j * 8;
    const __half* bS1 = g_w1t + (size_t)(n0 + r1) * ENCD + j * 8;
    const uint32_t aD0 = sb + OFF_A + r0 * 80 + j * 16;
    const uint32_t aD1 = sb + OFF_A + r1 * 80 + j * 16;
    const uint32_t bD0 = sb + OFF_B + r0 * 80 + j * 16;
    const uint32_t bD1 = sb + OFF_B + r1 * 80 + j * 16;

    #define ISSUE(s)                                                         \
        do {                                                                 \
            const uint32_t _rb = ((s) & 3) * ASTG;                           \
            const int _ko = (s) * 32;                                        \
            CP_ASYNC16(aD0 + _rb, aS0 + _ko);                                \
            CP_ASYNC16(aD1 + _rb, aS1 + _ko);                                \
            CP_ASYNC16(bD0 + _rb, bS0 + _ko);                                \
            CP_ASYNC16(bD1 + _rb, bS1 + _ko);                                \
        } while (0)

    float acc[4][4][4];
    #pragma unroll
    for (int mi = 0; mi < 4; mi++)
        #pragma unroll
        for (int ni = 0; ni < 4; ni++)
            #pragma unroll
            for (int r = 0; r < 4; r++) acc[mi][ni][r] = 0.f;

    ISSUE(0); CP_COMMIT();
    ISSUE(1); CP_COMMIT();

    for (int s = 0; s < NSTG; s++) {
        if (s + 2 < NSTG) ISSUE(s + 2);
        CP_COMMIT();
        CP_WAIT2();
        __syncthreads();

        const uint32_t stg = (s & 3) * ASTG;
        #pragma unroll
        for (int kh = 0; kh < 2; kh++) {
            const uint32_t kb = stg + kh * 32;
            uint32_t af[4][4], bf[4][2];
            #pragma unroll
            for (int mi = 0; mi < 4; mi++)
                LDSM4(af[mi][0], af[mi][1], af[mi][2], af[mi][3],
                      aTile + mi * 1280 + kb);
            LDSM4(bf[0][0], bf[1][0], bf[0][1], bf[1][1], bTile + kb);
            LDSM4(bf[2][0], bf[3][0], bf[2][1], bf[3][1], bTile + 1280 + kb);
            #pragma unroll
            for (int mi = 0; mi < 4; mi++)
                #pragma unroll
                for (int ni = 0; ni < 4; ni++)
                    mma_f16(acc[mi][ni], af[mi], bf[ni]);
        }
    }

    float rs0[4], rs1[4];
    #pragma unroll
    for (int mi = 0; mi < 4; mi++) {
        float s0 = 0.f, s1 = 0.f;
        #pragma unroll
        for (int ni = 0; ni < 4; ni++) {
            const int n_ = wn * 32 + ni * 8 + c * 2;
            const float q0 = qs[n_], q1 = qs[n_ + 1];
            const float v0 = vs[n_], v1 = vs[n_ + 1];
            s0 += tanh_fast(acc[mi][ni][0] + q0) * v0
                + tanh_fast(acc[mi][ni][1] + q1) * v1;
            s1 += tanh_fast(acc[mi][ni][2] + q0) * v0
                + tanh_fast(acc[mi][ni][3] + q1) * v1;
        }
        s0 += __shfl_xor_sync(0xffffffffu, s0, 1);
        s0 += __shfl_xor_sync(0xffffffffu, s0, 2);
        s1 += __shfl_xor_sync(0xffffffffu, s1, 1);
        s1 += __shfl_xor_sync(0xffffffffu, s1, 2);
        rs0[mi] = s0; rs1[mi] = s1;
    }
    if (c == 0) {
        #pragma unroll
        for (int mi = 0; mi < 4; mi++) {
            sred[wn * 128 + wm * 64 + mi * 16 + g]     = rs0[mi];
            sred[wn * 128 + wm * 64 + mi * 16 + g + 8] = rs1[mi];
        }
    }
    __syncthreads();
    if (t < 128)
        g_partials[(size_t)nt * MTOT + m0 + t] =
            (sred[t] + sred[128 + t]) + (sred[256 + t] + sred[384 + t]);
}

// ---------------------------------------------------------------------------
// K3: sum NTILES partials (fixed order), softmax over S per batch.
// ---------------------------------------------------------------------------
__global__ __launch_bounds__(256)
void k3_softmax() {
    __shared__ float red[256];
    const int b = blockIdx.x, t = threadIdx.x;
    float sc[8];
    float mx = -1e30f;
    #pragma unroll
    for (int i = 0; i < 8; i++) {
        const int s = t + 256 * i;
        float v0 = 0.f;
        #pragma unroll
        for (int nt = 0; nt < NTILES; nt++)
            v0 += g_partials[(size_t)nt * MTOT + b * SEQ + s];
        sc[i] = v0;
        mx = fmaxf(mx, v0);
    }
    red[t] = mx; __syncthreads();
    for (int o = 128; o > 0; o >>= 1) {
        if (t < o) red[t] = fmaxf(red[t], red[t + o]);
        __syncthreads();
    }
    mx = red[0]; __syncthreads();
    float sum = 0.f;
    #pragma unroll
    for (int i = 0; i < 8; i++) { sc[i] = expf(sc[i] - mx); sum += sc[i]; }
    red[t] = sum; __syncthreads();
    for (int o = 128; o > 0; o >>= 1) {
        if (t < o) red[t] += red[t + o];
        __syncthreads();
    }
    const float inv = 1.f / red[0];
    #pragma unroll
    for (int i = 0; i < 8; i++)
        g_attn[b * SEQ + t + 256 * i] = sc[i] * inv;
}

// ---------------------------------------------------------------------------
// K4: partial context over S-chunks of 128; thread owns 4 consecutive e
// (one LDG.64 per s). grid (32, 16) = (b, sc), 256 thr -> 1024 e/block.
// ---------------------------------------------------------------------------
__global__ __launch_bounds__(256)
void k4_context() {
    __shared__ float sat[128];
    const int b  = blockIdx.x;
    const int sc = blockIdx.y;
    const int t  = threadIdx.x;
    const int e0 = t * 4;
    const int sbase = sc * 128;
    if (t < 128) sat[t] = g_attn[b * SEQ + sbase + t];
    __syncthreads();
    const uint2* ep = (const uint2*)
        (g_ench + ((size_t)b * SEQ + sbase) * ENCD + e0);
    float a0 = 0.f, a1 = 0.f, a2 = 0.f, a3 = 0.f;
    #pragma unroll 8
    for (int s = 0; s < 128; s++) {
        const uint2 u = ep[(size_t)s * (ENCD / 4)];
        const float wgt = sat[s];
        const float2 f0 = __half22float2(*(const __half2*)&u.x);
        const float2 f1 = __half22float2(*(const __half2*)&u.y);
        a0 += wgt * f0.x; a1 += wgt * f0.y;
        a2 += wgt * f1.x; a3 += wgt * f1.y;
    }
    float* dst = &g_ctx[sc][b * ENCD + e0];
    dst[0] = a0; dst[1] = a1; dst[2] = a2; dst[3] = a3;
}

__global__ __launch_bounds__(256)
void k5_reduce(float* __restrict__ out) {
    const int i = blockIdx.x * 256 + threadIdx.x;
    float s = 0.f;
    #pragma unroll
    for (int ch = 0; ch < NCHUNK; ch++) s += g_ctx[ch][i];
    out[i] = s;
}

// ---------------------------------------------------------------------------
extern "C" void kernel_launch(void* const* d_in, const int* in_sizes, int n_in,
                              void* d_out, int out_size) {
    const float* enc = (const float*)d_in[0];
    const float* dec = (const float*)d_in[1];
    const float* w1  = (const float*)d_in[2];
    const float* b1  = (const float*)d_in[3];
    const float* w2  = (const float*)d_in[4];
    const float* b2  = (const float*)d_in[5];
    const float* v   = (const float*)d_in[6];
    float* out = (float*)d_out;

    cudaFuncSetAttribute(k2_scores, cudaFuncAttributeMaxDynamicSharedMemorySize,
                         SMTOT);

    k0_prep<<<NB_PREP, 256>>>(enc, w1, dec, w2, b1, b2);
    k2_scores<<<dim3(NTILES, 512), 256, SMTOT>>>(v);
    k3_softmax<<<32, 256>>>();
    k4_context<<<dim3(32, NCHUNK), 256>>>();
    k5_reduce<<<128, 256>>>(out);
}